// round 1
// baseline (speedup 1.0000x reference)
#include <cuda_runtime.h>
#include <cuda_bf16.h>
#include <cstdint>
#include <cstdio>

// Problem dims
#define BB   2048
#define TT   128
#define FF   64
#define HH   512
#define G4   2048   // 4*H

// GEMM tile config
#define BM   128
#define BN   128    // = 32 h-cols x 4 gates
#define BK   16
#define NTHREADS 256
#define ASTRIDE 20   // 16 + 4 pad, conflict-free A frag loads
#define BSTRIDE 136  // 128 + 8 pad, conflict-free B frag loads
#define GSTRIDE 132  // gate staging stride

// Persistent state (device globals: the sanctioned scratch mechanism)
__device__ float g_h1[2][BB * HH];
__device__ float g_c1[BB * HH];
__device__ float g_h2[2][BB * HH];
__device__ float g_c2[BB * HH];

struct SMemMM {
    float A[2][BM * ASTRIDE];   // 2*2560 floats
    float B[2][BK * BSTRIDE];   // 2*2176 floats
};
union SMemU {
    SMemMM mm;
    float gs[64 * GSTRIDE];     // gate staging: 64 rows x 128 cols (+pad)
};

__device__ __forceinline__ float to_tf32(float x) {
    uint32_t u;
    asm("cvt.rna.tf32.f32 %0, %1;" : "=r"(u) : "f"(x));
    return __uint_as_float(u);
}

__device__ __forceinline__ void mma8(float* d, const uint32_t* a, const uint32_t* b) {
    asm volatile(
        "mma.sync.aligned.m16n8k8.row.col.f32.tf32.tf32.f32 "
        "{%0,%1,%2,%3}, {%4,%5,%6,%7}, {%8,%9}, {%0,%1,%2,%3};\n"
        : "+f"(d[0]), "+f"(d[1]), "+f"(d[2]), "+f"(d[3])
        : "r"(a[0]), "r"(a[1]), "r"(a[2]), "r"(a[3]),
          "r"(b[0]), "r"(b[1]));
}

// Fused LSTM step: gates = [Ax | Ah] @ [Wx ; Wu] + bias, then cell update.
// Ax: [2048 x Kx] rows strided by sAx (Kx = 16*KxT)
// Ah: [2048 x 512] (KhT = 32 tiles, or 0 at t=0)
// Wx/Wu: row-major [K, 2048], gate blocks of 512 cols in order i,f,c,o
__global__ __launch_bounds__(NTHREADS) void lstm_step_kernel(
    const float* __restrict__ Ax, int sAx, int KxT,
    const float* __restrict__ Ah, int KhT,
    const float* __restrict__ Wx, const float* __restrict__ Wu,
    const float* __restrict__ bias,
    float* __restrict__ cbuf, int zero_c,
    float* __restrict__ hout)
{
    __shared__ __align__(16) SMemU sm;

    const int tid    = threadIdx.x;
    const int lane   = tid & 31;
    const int warp   = tid >> 5;
    const int warp_m = warp >> 2;   // 0..1  (64 rows each)
    const int warp_n = warp & 3;    // 0..3  (32 cols each)
    const int gid    = lane >> 2;   // 0..7
    const int tig    = lane & 3;    // 0..3
    const int bm     = blockIdx.x * BM;
    const int h0     = blockIdx.y * 32;
    const int KT     = KxT + KhT;

    float acc[4][4][4] = {};

    // ---- tile loaders (global -> regs) ----
    const int a_row  = tid >> 2;        // 0..63
    const int a_c4   = (tid & 3) * 4;   // col offset in tile
    const int b_row  = tid >> 5;        // 0..7
    const int b_j4   = tid & 31;
    const int b_col  = (b_j4 >> 3) * 512 + h0 + (b_j4 & 7) * 4; // W column for tile col j4*4

    float4 pa0, pa1, pb0, pb1;

    auto load_tiles = [&](int kt) {
        const float* asrc; int astr; int krow;
        const float* wsrc;
        if (kt < KxT) { asrc = Ax; astr = sAx; krow = kt * BK; wsrc = Wx; }
        else          { asrc = Ah; astr = HH;  krow = (kt - KxT) * BK; wsrc = Wu; }
        pa0 = *(const float4*)(asrc + (size_t)(bm + a_row)      * astr + krow + a_c4);
        pa1 = *(const float4*)(asrc + (size_t)(bm + a_row + 64) * astr + krow + a_c4);
        pb0 = *(const float4*)(wsrc + (size_t)(krow + b_row)     * G4 + b_col);
        pb1 = *(const float4*)(wsrc + (size_t)(krow + b_row + 8) * G4 + b_col);
    };

    auto store_tiles = [&](int buf) {
        float* Ap0 = &sm.mm.A[buf][a_row * ASTRIDE + a_c4];
        float* Ap1 = &sm.mm.A[buf][(a_row + 64) * ASTRIDE + a_c4];
        *(float4*)Ap0 = make_float4(to_tf32(pa0.x), to_tf32(pa0.y), to_tf32(pa0.z), to_tf32(pa0.w));
        *(float4*)Ap1 = make_float4(to_tf32(pa1.x), to_tf32(pa1.y), to_tf32(pa1.z), to_tf32(pa1.w));
        float* Bp0 = &sm.mm.B[buf][b_row * BSTRIDE + b_j4 * 4];
        float* Bp1 = &sm.mm.B[buf][(b_row + 8) * BSTRIDE + b_j4 * 4];
        *(float4*)Bp0 = make_float4(to_tf32(pb0.x), to_tf32(pb0.y), to_tf32(pb0.z), to_tf32(pb0.w));
        *(float4*)Bp1 = make_float4(to_tf32(pb1.x), to_tf32(pb1.y), to_tf32(pb1.z), to_tf32(pb1.w));
    };

    auto compute = [&](int buf) {
        const float* As = sm.mm.A[buf];
        const float* Bs = sm.mm.B[buf];
#pragma unroll
        for (int kk = 0; kk < 2; kk++) {
            uint32_t afr[4][4];
            uint32_t bfr[4][2];
            const int c = kk * 8 + tig;
#pragma unroll
            for (int mm = 0; mm < 4; mm++) {
                int r0 = warp_m * 64 + mm * 16 + gid;
                afr[mm][0] = __float_as_uint(As[r0 * ASTRIDE + c]);
                afr[mm][1] = __float_as_uint(As[(r0 + 8) * ASTRIDE + c]);
                afr[mm][2] = __float_as_uint(As[r0 * ASTRIDE + c + 4]);
                afr[mm][3] = __float_as_uint(As[(r0 + 8) * ASTRIDE + c + 4]);
            }
#pragma unroll
            for (int nn = 0; nn < 4; nn++) {
                int col = warp_n * 32 + nn * 8 + gid;
                bfr[nn][0] = __float_as_uint(Bs[c * BSTRIDE + col]);
                bfr[nn][1] = __float_as_uint(Bs[(c + 4) * BSTRIDE + col]);
            }
#pragma unroll
            for (int mm = 0; mm < 4; mm++)
#pragma unroll
                for (int nn = 0; nn < 4; nn++)
                    mma8(acc[mm][nn], afr[mm], bfr[nn]);
        }
    };

    // ---- main loop: double-buffered ----
    load_tiles(0);
    store_tiles(0);
    __syncthreads();
#pragma unroll 1
    for (int kt = 0; kt < KT; kt++) {
        const int buf = kt & 1;
        const bool more = (kt + 1 < KT);
        if (more) load_tiles(kt + 1);
        compute(buf);
        if (more) store_tiles(buf ^ 1);
        __syncthreads();
    }

    // ---- epilogue: stage gates through smem (2 chunks of 64 rows), cell update ----
#pragma unroll 1
    for (int chunk = 0; chunk < 2; chunk++) {
        if (warp_m == chunk) {
#pragma unroll
            for (int mm = 0; mm < 4; mm++) {
#pragma unroll
                for (int nn = 0; nn < 4; nn++) {
                    int r = mm * 16 + gid;
                    int cb = warp_n * 32 + nn * 8 + 2 * tig;
                    sm.gs[r * GSTRIDE + cb]           = acc[mm][nn][0];
                    sm.gs[r * GSTRIDE + cb + 1]       = acc[mm][nn][1];
                    sm.gs[(r + 8) * GSTRIDE + cb]     = acc[mm][nn][2];
                    sm.gs[(r + 8) * GSTRIDE + cb + 1] = acc[mm][nn][3];
                }
            }
        }
        __syncthreads();
#pragma unroll
        for (int i = 0; i < 8; i++) {
            int q = tid + i * 256;     // 0..2047 over 64x32 cells
            int r = q >> 5;
            int h = q & 31;
            int gh = h0 + h;
            float gi = sm.gs[r * GSTRIDE + h]      + bias[gh];
            float gf = sm.gs[r * GSTRIDE + 32 + h] + bias[512 + gh];
            float gc = sm.gs[r * GSTRIDE + 64 + h] + bias[1024 + gh];
            float go = sm.gs[r * GSTRIDE + 96 + h] + bias[1536 + gh];
            gi = 1.f / (1.f + __expf(-gi));
            gf = 1.f / (1.f + __expf(-gf));
            go = 1.f / (1.f + __expf(-go));
            gc = fmaxf(gc, 0.f);
            size_t ci = (size_t)(bm + chunk * 64 + r) * HH + gh;
            float cold = zero_c ? 0.f : cbuf[ci];
            float cn = gf * cold + gi * gc;
            cbuf[ci] = cn;
            hout[ci] = go * fmaxf(cn, 0.f);
        }
        __syncthreads();
    }
}

// Final dense head: out[b] = h2[b,:] . Wd + bd
__global__ __launch_bounds__(256) void dense_kernel(
    const float* __restrict__ h2, const float* __restrict__ Wd,
    const float* __restrict__ bd, float* __restrict__ out)
{
    int row  = blockIdx.x * 8 + (threadIdx.x >> 5);
    int lane = threadIdx.x & 31;
    const float* hr = h2 + (size_t)row * HH;
    float s = 0.f;
#pragma unroll
    for (int k = lane; k < HH; k += 32) s += hr[k] * Wd[k];
#pragma unroll
    for (int o = 16; o; o >>= 1) s += __shfl_xor_sync(0xffffffffu, s, o);
    if (lane == 0) out[row] = s + bd[0];
}

extern "C" void kernel_launch(void* const* d_in, const int* in_sizes, int n_in,
                              void* d_out, int out_size)
{
    (void)in_sizes; (void)n_in; (void)out_size;
    const float* x  = (const float*)d_in[0];
    const float* W1 = (const float*)d_in[1];
    const float* U1 = (const float*)d_in[2];
    const float* b1 = (const float*)d_in[3];
    const float* W2 = (const float*)d_in[4];
    const float* U2 = (const float*)d_in[5];
    const float* b2 = (const float*)d_in[6];
    const float* Wd = (const float*)d_in[7];
    const float* bd = (const float*)d_in[8];

    float *ph1, *pc1, *ph2, *pc2;
    cudaGetSymbolAddress((void**)&ph1, g_h1);
    cudaGetSymbolAddress((void**)&pc1, g_c1);
    cudaGetSymbolAddress((void**)&ph2, g_h2);
    cudaGetSymbolAddress((void**)&pc2, g_c2);

    float* h1buf[2] = { ph1, ph1 + (size_t)BB * HH };
    float* h2buf[2] = { ph2, ph2 + (size_t)BB * HH };

    dim3 grid(BB / BM, HH / 32);   // 16 x 16
    for (int t = 0; t < TT; t++) {
        int khT   = (t == 0) ? 0 : (HH / BK);
        int zeroc = (t == 0) ? 1 : 0;
        // Layer 1: A = [x_t | h1_prev]
        lstm_step_kernel<<<grid, NTHREADS>>>(
            x + (size_t)t * FF, TT * FF, FF / BK,
            h1buf[t & 1], khT,
            W1, U1, b1,
            pc1, zeroc,
            h1buf[(t + 1) & 1]);
        // Layer 2: A = [h1_t | h2_prev]
        lstm_step_kernel<<<grid, NTHREADS>>>(
            h1buf[(t + 1) & 1], HH, HH / BK,
            h2buf[t & 1], khT,
            W2, U2, b2,
            pc2, zeroc,
            h2buf[(t + 1) & 1]);
    }
    // t=127 writes h2buf[(127+1)&1] = h2buf[0]
    dense_kernel<<<BB / 8, 256>>>(h2buf[0], Wd, bd, (float*)d_out);
}